// round 5
// baseline (speedup 1.0000x reference)
#include <cuda_runtime.h>
#include <cuda_bf16.h>
#include <math.h>
#include <stdint.h>

// ---------------- problem constants ----------------
#define BB 4096
#define KK 32
#define SD 512          // STATE_DIM
#define ED 128          // ENC_DIM
#define HH 128          // H
#define G4 512          // 4*H
#define RR (BB*KK)      // 131072 rows
#define MLPIN 1024
#define H1 1024
#define H2 512
#define NCH 64          // BN reduction chunks

// ---------------- device scratch ----------------
__device__ float g_XPf[(size_t)RR*G4];   // 268MB  x_proj forward
__device__ float g_XPr[(size_t)RR*G4];   // 268MB  x_proj reverse
__device__ float g_X  [(size_t)RR*MLPIN];// 536MB  MLP input (S|Of|Or|V|A)
__device__ float g_Y1 [(size_t)RR*H1];   // 536MB
__device__ float g_Y2 [(size_t)RR*H2];   // 268MB
__device__ float g_hf[BB*HH], g_cf[BB*HH], g_hr[BB*HH], g_cr[BB*HH];
__device__ float g_gf[BB*G4], g_gr[BB*G4];
__device__ float g_psum[NCH*H1], g_psq[NCH*H1];
__device__ float g_mean[H1], g_istd[H1];
__device__ float g_regpart[18*16];

// ---------------- generic fp32 GEMM: C[M,N] = A[M,K] * W[N,K]^T + bias ----------------
// z-batched (up to 2 independent problems of identical shape per launch)
struct GemmPair {
    const float* A[2];
    const float* W[2];
    const float* bias0[2];
    const float* bias1[2];
    float*       C[2];
};

#define TBM 128
#define TBN 128
#define TBK 8

__global__ __launch_bounds__(256, 2)
void gemm_nt(GemmPair P, int M, int N, int Kdim) {
    const int z = blockIdx.z;
    const float* A  = P.A[z];
    const float* W  = P.W[z];
    const float* b0 = P.bias0[z];
    const float* b1 = P.bias1[z];
    float*       C  = P.C[z];

    __shared__ float As[TBK][TBM];
    __shared__ float Ws[TBK][TBN];

    const int tid  = threadIdx.x;
    const int brow = blockIdx.y * TBM;
    const int bcol = blockIdx.x * TBN;

    const int ldr = tid >> 1;          // 0..127
    const int ldc = (tid & 1) * 4;     // 0 or 4

    const float* Aptr = A + (size_t)(brow + ldr) * Kdim + ldc;
    const float* Wptr = W + (size_t)(bcol + ldr) * Kdim + ldc;

    const int ty = tid >> 4;  // 0..15
    const int tx = tid & 15;  // 0..15

    float acc[8][8];
    #pragma unroll
    for (int i = 0; i < 8; i++)
        #pragma unroll
        for (int j = 0; j < 8; j++) acc[i][j] = 0.f;

    for (int k0 = 0; k0 < Kdim; k0 += TBK) {
        float4 av = *(const float4*)(Aptr);
        float4 wv = *(const float4*)(Wptr);
        As[ldc+0][ldr] = av.x; As[ldc+1][ldr] = av.y;
        As[ldc+2][ldr] = av.z; As[ldc+3][ldr] = av.w;
        Ws[ldc+0][ldr] = wv.x; Ws[ldc+1][ldr] = wv.y;
        Ws[ldc+2][ldr] = wv.z; Ws[ldc+3][ldr] = wv.w;
        __syncthreads();

        #pragma unroll
        for (int kk = 0; kk < TBK; kk++) {
            float ra[8], rw[8];
            #pragma unroll
            for (int i = 0; i < 4; i++) {
                ((float4*)ra)[0] = *(const float4*)&As[kk][ty*8];
                ((float4*)ra)[1] = *(const float4*)&As[kk][ty*8+4];
                ((float4*)rw)[0] = *(const float4*)&Ws[kk][tx*8];
                ((float4*)rw)[1] = *(const float4*)&Ws[kk][tx*8+4];
                break;
            }
            #pragma unroll
            for (int i = 0; i < 8; i++)
                #pragma unroll
                for (int j = 0; j < 8; j++)
                    acc[i][j] += ra[i] * rw[j];
        }
        __syncthreads();
        Aptr += TBK;
        Wptr += TBK;
    }

    // epilogue (+ optional column biases)
    #pragma unroll
    for (int i = 0; i < 8; i++) {
        const int r = brow + ty*8 + i;
        float* crow = C + (size_t)r * N + bcol + tx*8;
        float4 o0, o1;
        float vj[8];
        #pragma unroll
        for (int j = 0; j < 8; j++) {
            float badd = 0.f;
            const int c = bcol + tx*8 + j;
            if (b0) badd += b0[c];
            if (b1) badd += b1[c];
            vj[j] = acc[i][j] + badd;
        }
        o0.x = vj[0]; o0.y = vj[1]; o0.z = vj[2]; o0.w = vj[3];
        o1.x = vj[4]; o1.y = vj[5]; o1.z = vj[6]; o1.w = vj[7];
        *(float4*)(crow)     = o0;
        *(float4*)(crow + 4) = o1;
    }
}

// ---------------- LSTM init ----------------
__global__ void zero_hc() {
    int i = blockIdx.x * blockDim.x + threadIdx.x;
    if (i < BB*HH) { g_hf[i] = 0.f; g_cf[i] = 0.f; g_hr[i] = 0.f; g_cr[i] = 0.f; }
}

// ---------------- fused LSTM elementwise step ----------------
__global__ void lstm_elem(int t) {
    const int z = blockIdx.z;                         // 0 fwd, 1 rev
    const int idx = blockIdx.x * blockDim.x + threadIdx.x;  // over B*H
    if (idx >= BB*HH) return;
    const int b = idx >> 7;
    const int j = idx & 127;
    const int k = z ? (KK - 1 - t) : t;

    const float* G  = z ? g_gr  : g_gf;
    const float* XP = z ? g_XPr : g_XPf;
    float* hbuf = z ? g_hr : g_hf;
    float* cbuf = z ? g_cr : g_cf;

    const size_t r = (size_t)b * KK + k;
    const float* xp = XP + r * G4;
    const float* gg = G  + (size_t)b * G4;

    float zi = xp[j]       + gg[j];
    float zf = xp[128 + j] + gg[128 + j];
    float zg = xp[256 + j] + gg[256 + j];
    float zo = xp[384 + j] + gg[384 + j];

    float si = 1.f / (1.f + expf(-zi));
    float sf = 1.f / (1.f + expf(-zf));
    float so = 1.f / (1.f + expf(-zo));

    float c = cbuf[idx];
    float cn = sf * c + si * tanhf(zg);
    float hn = so * tanhf(cn);
    cbuf[idx] = cn;
    hbuf[idx] = hn;

    const int colbase = z ? 640 : 512;   // Of at 512:640, Or at 640:768
    g_X[r * MLPIN + colbase + j] = hn;
}

// ---------------- fill X with state + V ----------------
__global__ void fill_X(const float* __restrict__ state, const float* __restrict__ action) {
    const int r = blockIdx.x;            // 0..RR-1
    const int tid = threadIdx.x;         // 128
    const int b = r >> 5;
    float* xrow = g_X + (size_t)r * MLPIN;
    const float* srow = state + (size_t)b * SD;
    #pragma unroll
    for (int c = tid; c < SD; c += 128) xrow[c] = srow[c];
    xrow[768 + tid] = action[(size_t)r * ED + tid];
}

// ---------------- self-attention (per batch row, 32x32) ----------------
__global__ void attn_kernel(const float* __restrict__ V) {
    const int b = blockIdx.x;
    __shared__ float sV[32][129];
    __shared__ float sS[32][33];
    const int tid = threadIdx.x;  // 128
    const float* Vb = V + (size_t)b * KK * ED;

    for (int i = tid; i < KK * ED; i += 128) sV[i >> 7][i & 127] = Vb[i];
    __syncthreads();

    for (int idx = tid; idx < KK * KK; idx += 128) {
        const int r = idx >> 5, c = idx & 31;
        float s = 0.f;
        #pragma unroll 8
        for (int d = 0; d < ED; d++) s += sV[r][d] * sV[c][d];
        sS[r][c] = s;
    }
    __syncthreads();

    if (tid < KK) {
        float mx = -1e30f;
        for (int c = 0; c < KK; c++) mx = fmaxf(mx, sS[tid][c]);
        float sum = 0.f;
        for (int c = 0; c < KK; c++) { float e = expf(sS[tid][c] - mx); sS[tid][c] = e; sum += e; }
        float inv = 1.f / sum;
        for (int c = 0; c < KK; c++) sS[tid][c] *= inv;
    }
    __syncthreads();

    const int d = tid;  // 0..127
    for (int kq = 0; kq < KK; kq++) {
        float a = 0.f;
        #pragma unroll 8
        for (int l = 0; l < KK; l++) a += sS[kq][l] * sV[l][d];
        const size_t r = (size_t)b * KK + kq;
        g_X[r * MLPIN + 896 + d] = a;
    }
}

// ---------------- batchnorm (deterministic two-pass) ----------------
__global__ void bn_partial(const float* __restrict__ Y, int cols) {
    const int c  = blockIdx.x * 128 + threadIdx.x;
    const int ch = blockIdx.y;
    const int rows_per = RR / NCH;     // 2048
    const size_t r0 = (size_t)ch * rows_per;
    float s = 0.f, s2 = 0.f;
    const float* p = Y + r0 * cols + c;
    for (int i = 0; i < rows_per; i++) {
        float v = p[(size_t)i * cols];
        s += v; s2 += v * v;
    }
    g_psum[ch * cols + c] = s;
    g_psq [ch * cols + c] = s2;
}

__global__ void bn_finalize(int cols) {
    const int c = blockIdx.x * 128 + threadIdx.x;
    float s = 0.f, s2 = 0.f;
    for (int ch = 0; ch < NCH; ch++) { s += g_psum[ch * cols + c]; s2 += g_psq[ch * cols + c]; }
    const float mu  = s  / (float)RR;
    const float var = s2 / (float)RR - mu * mu;
    g_mean[c] = mu;
    g_istd[c] = rsqrtf(var + 1e-5f);
}

__global__ void bn_apply_relu(float* Y, const float* __restrict__ gamma,
                              const float* __restrict__ beta, int cols) {
    const size_t total = (size_t)RR * cols;
    const int mask = cols - 1;  // cols is power of 2
    size_t i = (size_t)blockIdx.x * blockDim.x + threadIdx.x;
    const size_t stride = (size_t)gridDim.x * blockDim.x;
    for (; i < total; i += stride) {
        const int c = (int)(i & mask);
        float v = (Y[i] - g_mean[c]) * g_istd[c] * gamma[c] + beta[c];
        Y[i] = v > 0.f ? v : 0.f;
    }
}

// ---------------- final layer: Q = h2 @ W3^T + b3 ----------------
__global__ void final_q(const float* __restrict__ W3, const float* __restrict__ b3,
                        float* __restrict__ out) {
    const int gwarp = (blockIdx.x * blockDim.x + threadIdx.x) >> 5;
    const int lane  = threadIdx.x & 31;
    if (gwarp >= RR) return;
    const float* row = g_Y2 + (size_t)gwarp * H2;
    float s = 0.f;
    #pragma unroll
    for (int i = 0; i < H2 / 32; i++) {
        const int c = i * 32 + lane;
        s += row[c] * W3[c];
    }
    #pragma unroll
    for (int o = 16; o; o >>= 1) s += __shfl_xor_sync(0xffffffffu, s, o);
    if (lane == 0) out[gwarp] = s + b3[0];
}

// ---------------- regularizer ----------------
struct RegArgs { const float* p[18]; int n[18]; };

__global__ void reg_partial(RegArgs ra) {
    const int pi = blockIdx.x;   // 0..17
    const int ch = blockIdx.y;   // 0..15
    __shared__ float red[256];
    const float* p = ra.p[pi];
    const int n = ra.n[pi];
    const int per = (n + 15) / 16;
    const int lo = ch * per;
    const int hi = min(n, lo + per);
    float s = 0.f;
    for (int i = lo + threadIdx.x; i < hi; i += 256) { float v = p[i]; s += v * v; }
    red[threadIdx.x] = s;
    __syncthreads();
    for (int o = 128; o; o >>= 1) {
        if (threadIdx.x < o) red[threadIdx.x] += red[threadIdx.x + o];
        __syncthreads();
    }
    if (threadIdx.x == 0) g_regpart[pi * 16 + ch] = red[0] / (float)n;
}

__global__ void reg_final(float* out, int out_size) {
    if (threadIdx.x == 0 && blockIdx.x == 0) {
        float s = 0.f;
        for (int i = 0; i < 18 * 16; i++) s += g_regpart[i];
        if (out_size > RR) out[RR] = s;
    }
}

// ---------------- launch ----------------
extern "C" void kernel_launch(void* const* d_in, const int* in_sizes, int n_in,
                              void* d_out, int out_size) {
    const float* state  = (const float*)d_in[0];
    const float* action = (const float*)d_in[1];
    const float* w_ih_f = (const float*)d_in[2];
    const float* w_hh_f = (const float*)d_in[3];
    const float* b_ih_f = (const float*)d_in[4];
    const float* b_hh_f = (const float*)d_in[5];
    const float* w_ih_r = (const float*)d_in[6];
    const float* w_hh_r = (const float*)d_in[7];
    const float* b_ih_r = (const float*)d_in[8];
    const float* b_hh_r = (const float*)d_in[9];
    const float* W1 = (const float*)d_in[10];
    const float* b1 = (const float*)d_in[11];
    const float* g1 = (const float*)d_in[12];
    const float* be1 = (const float*)d_in[13];
    const float* W2 = (const float*)d_in[14];
    const float* b2 = (const float*)d_in[15];
    const float* g2 = (const float*)d_in[16];
    const float* be2 = (const float*)d_in[17];
    const float* W3 = (const float*)d_in[18];
    const float* b3 = (const float*)d_in[19];
    float* out = (float*)d_out;

    // device scratch pointers
    float *pXPf, *pXPr, *pX, *pY1, *pY2, *phf, *phr, *pgf, *pgr;
    cudaGetSymbolAddress((void**)&pXPf, g_XPf);
    cudaGetSymbolAddress((void**)&pXPr, g_XPr);
    cudaGetSymbolAddress((void**)&pX,   g_X);
    cudaGetSymbolAddress((void**)&pY1,  g_Y1);
    cudaGetSymbolAddress((void**)&pY2,  g_Y2);
    cudaGetSymbolAddress((void**)&phf,  g_hf);
    cudaGetSymbolAddress((void**)&phr,  g_hr);
    cudaGetSymbolAddress((void**)&pgf,  g_gf);
    cudaGetSymbolAddress((void**)&pgr,  g_gr);

    // 1. init LSTM state
    zero_hc<<<(BB*HH + 255)/256, 256>>>();

    // 2. x_proj for both directions: [R,128] @ [512,128]^T + (b_ih + b_hh)
    {
        GemmPair P;
        P.A[0] = action;  P.A[1] = action;
        P.W[0] = w_ih_f;  P.W[1] = w_ih_r;
        P.bias0[0] = b_ih_f; P.bias1[0] = b_hh_f;
        P.bias0[1] = b_ih_r; P.bias1[1] = b_hh_r;
        P.C[0] = pXPf; P.C[1] = pXPr;
        gemm_nt<<<dim3(G4/TBN, RR/TBM, 2), 256>>>(P, RR, G4, ED);
    }

    // 3. fill X: state + V columns
    fill_X<<<RR, 128>>>(state, action);

    // 4. attention -> X[:,896:1024]
    attn_kernel<<<BB, 128>>>(action);

    // 5. LSTM recurrence, 32 steps, fwd+rev batched on z
    for (int t = 0; t < KK; t++) {
        GemmPair P;
        P.A[0] = phf; P.A[1] = phr;
        P.W[0] = w_hh_f; P.W[1] = w_hh_r;
        P.bias0[0] = nullptr; P.bias1[0] = nullptr;
        P.bias0[1] = nullptr; P.bias1[1] = nullptr;
        P.C[0] = pgf; P.C[1] = pgr;
        gemm_nt<<<dim3(G4/TBN, BB/TBM, 2), 256>>>(P, BB, G4, HH);
        lstm_elem<<<dim3((BB*HH + 255)/256, 1, 2), 256>>>(t);
    }

    // 6. MLP layer 1: Y1 = X @ W1^T + b1
    {
        GemmPair P;
        P.A[0] = pX; P.A[1] = pX;
        P.W[0] = W1; P.W[1] = W1;
        P.bias0[0] = b1; P.bias1[0] = nullptr;
        P.bias0[1] = b1; P.bias1[1] = nullptr;
        P.C[0] = pY1; P.C[1] = pY1;
        gemm_nt<<<dim3(H1/TBN, RR/TBM, 1), 256>>>(P, RR, H1, MLPIN);
    }
    bn_partial<<<dim3(H1/128, NCH), 128>>>(pY1, H1);
    bn_finalize<<<H1/128, 128>>>(H1);
    bn_apply_relu<<<2048, 256>>>(pY1, g1, be1, H1);

    // 7. MLP layer 2: Y2 = h1 @ W2^T + b2
    {
        GemmPair P;
        P.A[0] = pY1; P.A[1] = pY1;
        P.W[0] = W2; P.W[1] = W2;
        P.bias0[0] = b2; P.bias1[0] = nullptr;
        P.bias0[1] = b2; P.bias1[1] = nullptr;
        P.C[0] = pY2; P.C[1] = pY2;
        gemm_nt<<<dim3(H2/TBN, RR/TBM, 1), 256>>>(P, RR, H2, H1);
    }
    bn_partial<<<dim3(H2/128, NCH), 128>>>(pY2, H2);
    bn_finalize<<<H2/128, 128>>>(H2);
    bn_apply_relu<<<2048, 256>>>(pY2, g2, be2, H2);

    // 8. final layer
    final_q<<<(RR*32 + 255)/256, 256>>>(W3, b3, out);

    // 9. regularizer
    {
        RegArgs ra;
        for (int i = 0; i < 18; i++) {
            ra.p[i] = (const float*)d_in[2 + i];
            ra.n[i] = in_sizes[2 + i];
        }
        reg_partial<<<dim3(18, 16), 256>>>(ra);
        reg_final<<<1, 32>>>(out, out_size);
    }
}

// round 6
// speedup vs baseline: 2.6675x; 2.6675x over previous
#include <cuda_runtime.h>
#include <cuda_fp16.h>
#include <mma.h>
#include <math.h>
#include <stdint.h>

using namespace nvcuda;

// ---------------- problem constants ----------------
#define BB 4096
#define KK 32
#define SD 512          // STATE_DIM
#define ED 128          // ENC_DIM
#define HH 128          // H
#define G4 512          // 4*H
#define RR (BB*KK)      // 131072 rows
#define MLPIN 1024
#define H1 1024
#define H2 512
#define NCH 64          // BN reduction chunks

// ---------------- device scratch ----------------
__device__ float  g_XPf[(size_t)RR*G4];    // 268MB  x_proj forward (fp32)
__device__ float  g_XPr[(size_t)RR*G4];    // 268MB  x_proj reverse (fp32)
__device__ __half g_Xh [(size_t)RR*MLPIN]; // 268MB  MLP input fp16 (S|Of|Or|V|A)
__device__ float  g_Y1 [(size_t)RR*H1];    // 536MB  pre-BN layer1
__device__ __half g_H1h[(size_t)RR*H1];    // 268MB  post-BN+ReLU layer1 (fp16)
__device__ float  g_Y2 [(size_t)RR*H2];    // 268MB
__device__ float  g_hf[BB*HH], g_cf[BB*HH], g_hr[BB*HH], g_cr[BB*HH];
__device__ float  g_gf[BB*G4], g_gr[BB*G4];
__device__ float  g_psum[NCH*H1], g_psq[NCH*H1];
__device__ float  g_mean[H1], g_istd[H1];
__device__ float  g_regpart[18*16];
__device__ __half g_W1h[(size_t)H1*MLPIN];   // 2MB
__device__ __half g_W2h[(size_t)H2*H1];      // 1MB
__device__ __half g_wihfh[G4*ED], g_wihrh[G4*ED];

// ---------------- fp32 -> fp16 convert ----------------
__global__ void tohalf(const float* __restrict__ src, __half* __restrict__ dst, int n) {
    int i = blockIdx.x * blockDim.x + threadIdx.x;
    if (i < n) dst[i] = __float2half(src[i]);
}

// ---------------- fp16 tensor-core GEMM: C[M,N] = A[M,K] * B[N,K]^T ----------------
// A row-major (lda), B row-major [N,K] (ldb) -> B^T consumed as col_major.
// No bias (biases are folded elsewhere / BN-invariant). fp32 accumulate.
#define HBM_ 128
#define HBN_ 128
#define HBK_ 32
#define HLD_ 48   // smem row stride in halves (96B, 16B-aligned, deconflicted)

__global__ __launch_bounds__(256, 2)
void hgemm_nt(const __half* __restrict__ A, int lda,
              const __half* __restrict__ B, int ldb,
              float* __restrict__ C, int N, int K) {
    __shared__ __align__(16) __half As[HBM_ * HLD_];
    __shared__ __align__(16) __half Bs[HBN_ * HLD_];

    const int tid   = threadIdx.x;
    const int brow  = blockIdx.y * HBM_;
    const int bcol  = blockIdx.x * HBN_;
    const int warpid = tid >> 5;
    const int wm = warpid & 1;   // 0..1 -> 64-row slab
    const int wn = warpid >> 1;  // 0..3 -> 32-col slab

    wmma::fragment<wmma::accumulator, 16, 16, 16, float> c[4][2];
    #pragma unroll
    for (int i = 0; i < 4; i++)
        #pragma unroll
        for (int j = 0; j < 2; j++) wmma::fill_fragment(c[i][j], 0.0f);

    const int lr = tid >> 2;          // 0..63
    const int lc = (tid & 3) * 8;     // 0,8,16,24

    for (int k0 = 0; k0 < K; k0 += HBK_) {
        #pragma unroll
        for (int s = 0; s < 2; s++) {
            const int r = lr + s * 64;
            *(uint4*)&As[r * HLD_ + lc] =
                *(const uint4*)&A[(size_t)(brow + r) * lda + k0 + lc];
            *(uint4*)&Bs[r * HLD_ + lc] =
                *(const uint4*)&B[(size_t)(bcol + r) * ldb + k0 + lc];
        }
        __syncthreads();

        #pragma unroll
        for (int kk = 0; kk < HBK_; kk += 16) {
            wmma::fragment<wmma::matrix_a, 16, 16, 16, __half, wmma::row_major> af[4];
            wmma::fragment<wmma::matrix_b, 16, 16, 16, __half, wmma::col_major> bf[2];
            #pragma unroll
            for (int i = 0; i < 4; i++)
                wmma::load_matrix_sync(af[i], &As[(wm * 64 + i * 16) * HLD_ + kk], HLD_);
            #pragma unroll
            for (int j = 0; j < 2; j++)
                wmma::load_matrix_sync(bf[j], &Bs[(wn * 32 + j * 16) * HLD_ + kk], HLD_);
            #pragma unroll
            for (int i = 0; i < 4; i++)
                #pragma unroll
                for (int j = 0; j < 2; j++)
                    wmma::mma_sync(c[i][j], af[i], bf[j], c[i][j]);
        }
        __syncthreads();
    }

    #pragma unroll
    for (int i = 0; i < 4; i++)
        #pragma unroll
        for (int j = 0; j < 2; j++)
            wmma::store_matrix_sync(
                &C[(size_t)(brow + wm * 64 + i * 16) * N + bcol + wn * 32 + j * 16],
                c[i][j], N, wmma::mem_row_major);
}

// ---------------- fp32 GEMM for the serial LSTM recurrence ----------------
struct GemmPair {
    const float* A[2];
    const float* W[2];
    float*       C[2];
};

#define TBM 128
#define TBN 128
#define TBK 8

__global__ __launch_bounds__(256, 2)
void gemm_nt(GemmPair P, int N, int Kdim) {
    const int z = blockIdx.z;
    const float* A = P.A[z];
    const float* W = P.W[z];
    float*       C = P.C[z];

    __shared__ float As[TBK][TBM];
    __shared__ float Ws[TBK][TBN];

    const int tid  = threadIdx.x;
    const int brow = blockIdx.y * TBM;
    const int bcol = blockIdx.x * TBN;

    const int ldr = tid >> 1;
    const int ldc = (tid & 1) * 4;

    const float* Aptr = A + (size_t)(brow + ldr) * Kdim + ldc;
    const float* Wptr = W + (size_t)(bcol + ldr) * Kdim + ldc;

    const int ty = tid >> 4;
    const int tx = tid & 15;

    float acc[8][8];
    #pragma unroll
    for (int i = 0; i < 8; i++)
        #pragma unroll
        for (int j = 0; j < 8; j++) acc[i][j] = 0.f;

    for (int k0 = 0; k0 < Kdim; k0 += TBK) {
        float4 av = *(const float4*)(Aptr);
        float4 wv = *(const float4*)(Wptr);
        As[ldc+0][ldr] = av.x; As[ldc+1][ldr] = av.y;
        As[ldc+2][ldr] = av.z; As[ldc+3][ldr] = av.w;
        Ws[ldc+0][ldr] = wv.x; Ws[ldc+1][ldr] = wv.y;
        Ws[ldc+2][ldr] = wv.z; Ws[ldc+3][ldr] = wv.w;
        __syncthreads();

        #pragma unroll
        for (int kk = 0; kk < TBK; kk++) {
            float ra[8], rw[8];
            ((float4*)ra)[0] = *(const float4*)&As[kk][ty*8];
            ((float4*)ra)[1] = *(const float4*)&As[kk][ty*8+4];
            ((float4*)rw)[0] = *(const float4*)&Ws[kk][tx*8];
            ((float4*)rw)[1] = *(const float4*)&Ws[kk][tx*8+4];
            #pragma unroll
            for (int i = 0; i < 8; i++)
                #pragma unroll
                for (int j = 0; j < 8; j++)
                    acc[i][j] += ra[i] * rw[j];
        }
        __syncthreads();
        Aptr += TBK;
        Wptr += TBK;
    }

    #pragma unroll
    for (int i = 0; i < 8; i++) {
        const int r = brow + ty*8 + i;
        float* crow = C + (size_t)r * N + bcol + tx*8;
        *(float4*)(crow)     = make_float4(acc[i][0], acc[i][1], acc[i][2], acc[i][3]);
        *(float4*)(crow + 4) = make_float4(acc[i][4], acc[i][5], acc[i][6], acc[i][7]);
    }
}

// ---------------- LSTM init ----------------
__global__ void zero_hc() {
    int i = blockIdx.x * blockDim.x + threadIdx.x;
    if (i < BB*HH) { g_hf[i] = 0.f; g_cf[i] = 0.f; g_hr[i] = 0.f; g_cr[i] = 0.f; }
}

// ---------------- fused LSTM elementwise step (biases folded here) ----------------
__global__ void lstm_elem(int t,
                          const float* __restrict__ bihf, const float* __restrict__ bhhf,
                          const float* __restrict__ bihr, const float* __restrict__ bhhr) {
    const int z = blockIdx.z;                                // 0 fwd, 1 rev
    const int idx = blockIdx.x * blockDim.x + threadIdx.x;   // over B*H
    if (idx >= BB*HH) return;
    const int b = idx >> 7;
    const int j = idx & 127;
    const int k = z ? (KK - 1 - t) : t;

    const float* G   = z ? g_gr  : g_gf;
    const float* XP  = z ? g_XPr : g_XPf;
    const float* bih = z ? bihr : bihf;
    const float* bhh = z ? bhhr : bhhf;
    float* hbuf = z ? g_hr : g_hf;
    float* cbuf = z ? g_cr : g_cf;

    const size_t r = (size_t)b * KK + k;
    const float* xp = XP + r * G4;
    const float* gg = G  + (size_t)b * G4;

    float zi = xp[j]       + gg[j]       + bih[j]       + bhh[j];
    float zf = xp[128 + j] + gg[128 + j] + bih[128 + j] + bhh[128 + j];
    float zg = xp[256 + j] + gg[256 + j] + bih[256 + j] + bhh[256 + j];
    float zo = xp[384 + j] + gg[384 + j] + bih[384 + j] + bhh[384 + j];

    float si = 1.f / (1.f + expf(-zi));
    float sf = 1.f / (1.f + expf(-zf));
    float so = 1.f / (1.f + expf(-zo));

    float c = cbuf[idx];
    float cn = sf * c + si * tanhf(zg);
    float hn = so * tanhf(cn);
    cbuf[idx] = cn;
    hbuf[idx] = hn;

    const int colbase = z ? 640 : 512;   // Of at 512:640, Or at 640:768
    g_Xh[r * MLPIN + colbase + j] = __float2half(hn);
}

// ---------------- fill X (fp16) with state + V ----------------
__global__ void fill_X(const float* __restrict__ state, const float* __restrict__ action) {
    const int r = blockIdx.x;
    const int tid = threadIdx.x;     // 128
    const int b = r >> 5;
    __half* xrow = g_Xh + (size_t)r * MLPIN;
    const float* srow = state + (size_t)b * SD;
    #pragma unroll
    for (int c = tid; c < SD; c += 128) xrow[c] = __float2half(srow[c]);
    xrow[768 + tid] = __float2half(action[(size_t)r * ED + tid]);
}

// ---------------- self-attention (per batch row, 32x32) ----------------
__global__ void attn_kernel(const float* __restrict__ V) {
    const int b = blockIdx.x;
    __shared__ float sV[32][129];
    __shared__ float sS[32][33];
    const int tid = threadIdx.x;  // 128
    const float* Vb = V + (size_t)b * KK * ED;

    for (int i = tid; i < KK * ED; i += 128) sV[i >> 7][i & 127] = Vb[i];
    __syncthreads();

    for (int idx = tid; idx < KK * KK; idx += 128) {
        const int r = idx >> 5, c = idx & 31;
        float s = 0.f;
        #pragma unroll 8
        for (int d = 0; d < ED; d++) s += sV[r][d] * sV[c][d];
        sS[r][c] = s;
    }
    __syncthreads();

    if (tid < KK) {
        float mx = -1e30f;
        for (int c = 0; c < KK; c++) mx = fmaxf(mx, sS[tid][c]);
        float sum = 0.f;
        for (int c = 0; c < KK; c++) { float e = expf(sS[tid][c] - mx); sS[tid][c] = e; sum += e; }
        float inv = 1.f / sum;
        for (int c = 0; c < KK; c++) sS[tid][c] *= inv;
    }
    __syncthreads();

    const int d = tid;
    for (int kq = 0; kq < KK; kq++) {
        float a = 0.f;
        #pragma unroll 8
        for (int l = 0; l < KK; l++) a += sS[kq][l] * sV[l][d];
        const size_t r = (size_t)b * KK + kq;
        g_Xh[r * MLPIN + 896 + d] = __float2half(a);
    }
}

// ---------------- batchnorm (deterministic two-pass) ----------------
__global__ void bn_partial(const float* __restrict__ Y, int cols) {
    const int c  = blockIdx.x * 128 + threadIdx.x;
    const int ch = blockIdx.y;
    const int rows_per = RR / NCH;
    const size_t r0 = (size_t)ch * rows_per;
    float s = 0.f, s2 = 0.f;
    const float* p = Y + r0 * cols + c;
    for (int i = 0; i < rows_per; i++) {
        float v = p[(size_t)i * cols];
        s += v; s2 += v * v;
    }
    g_psum[ch * cols + c] = s;
    g_psq [ch * cols + c] = s2;
}

__global__ void bn_finalize(int cols) {
    const int c = blockIdx.x * 128 + threadIdx.x;
    float s = 0.f, s2 = 0.f;
    for (int ch = 0; ch < NCH; ch++) { s += g_psum[ch * cols + c]; s2 += g_psq[ch * cols + c]; }
    const float mu  = s  / (float)RR;
    const float var = s2 / (float)RR - mu * mu;
    g_mean[c] = mu;
    g_istd[c] = rsqrtf(var + 1e-5f);
}

// layer-1 variant: writes fp16 activations for the next tensor GEMM
__global__ void bn_apply_relu_h(const float* __restrict__ Y, __half* __restrict__ out,
                                const float* __restrict__ gamma,
                                const float* __restrict__ beta, int cols) {
    const size_t total = (size_t)RR * cols;
    const int mask = cols - 1;
    size_t i = (size_t)blockIdx.x * blockDim.x + threadIdx.x;
    const size_t stride = (size_t)gridDim.x * blockDim.x;
    for (; i < total; i += stride) {
        const int c = (int)(i & mask);
        float v = (Y[i] - g_mean[c]) * g_istd[c] * gamma[c] + beta[c];
        out[i] = __float2half(v > 0.f ? v : 0.f);
    }
}

// layer-2 variant: fp32 in place (final layer is fp32)
__global__ void bn_apply_relu(float* Y, const float* __restrict__ gamma,
                              const float* __restrict__ beta, int cols) {
    const size_t total = (size_t)RR * cols;
    const int mask = cols - 1;
    size_t i = (size_t)blockIdx.x * blockDim.x + threadIdx.x;
    const size_t stride = (size_t)gridDim.x * blockDim.x;
    for (; i < total; i += stride) {
        const int c = (int)(i & mask);
        float v = (Y[i] - g_mean[c]) * g_istd[c] * gamma[c] + beta[c];
        Y[i] = v > 0.f ? v : 0.f;
    }
}

// ---------------- final layer: Q = h2 @ W3^T + b3 ----------------
__global__ void final_q(const float* __restrict__ W3, const float* __restrict__ b3,
                        float* __restrict__ out) {
    const int gwarp = (blockIdx.x * blockDim.x + threadIdx.x) >> 5;
    const int lane  = threadIdx.x & 31;
    if (gwarp >= RR) return;
    const float* row = g_Y2 + (size_t)gwarp * H2;
    float s = 0.f;
    #pragma unroll
    for (int i = 0; i < H2 / 32; i++) {
        const int c = i * 32 + lane;
        s += row[c] * W3[c];
    }
    #pragma unroll
    for (int o = 16; o; o >>= 1) s += __shfl_xor_sync(0xffffffffu, s, o);
    if (lane == 0) out[gwarp] = s + b3[0];
}

// ---------------- regularizer ----------------
struct RegArgs { const float* p[18]; int n[18]; };

__global__ void reg_partial(RegArgs ra) {
    const int pi = blockIdx.x;
    const int ch = blockIdx.y;
    __shared__ float red[256];
    const float* p = ra.p[pi];
    const int n = ra.n[pi];
    const int per = (n + 15) / 16;
    const int lo = ch * per;
    const int hi = min(n, lo + per);
    float s = 0.f;
    for (int i = lo + threadIdx.x; i < hi; i += 256) { float v = p[i]; s += v * v; }
    red[threadIdx.x] = s;
    __syncthreads();
    for (int o = 128; o; o >>= 1) {
        if (threadIdx.x < o) red[threadIdx.x] += red[threadIdx.x + o];
        __syncthreads();
    }
    if (threadIdx.x == 0) g_regpart[pi * 16 + ch] = red[0] / (float)n;
}

__global__ void reg_final(float* out, int out_size) {
    if (threadIdx.x == 0 && blockIdx.x == 0) {
        float s = 0.f;
        for (int i = 0; i < 18 * 16; i++) s += g_regpart[i];
        if (out_size > RR) out[RR] = s;
    }
}

// ---------------- launch ----------------
extern "C" void kernel_launch(void* const* d_in, const int* in_sizes, int n_in,
                              void* d_out, int out_size) {
    const float* state  = (const float*)d_in[0];
    const float* action = (const float*)d_in[1];
    const float* w_ih_f = (const float*)d_in[2];
    const float* w_hh_f = (const float*)d_in[3];
    const float* b_ih_f = (const float*)d_in[4];
    const float* b_hh_f = (const float*)d_in[5];
    const float* w_ih_r = (const float*)d_in[6];
    const float* w_hh_r = (const float*)d_in[7];
    const float* b_ih_r = (const float*)d_in[8];
    const float* b_hh_r = (const float*)d_in[9];
    const float* W1 = (const float*)d_in[10];
    const float* W2 = (const float*)d_in[14];
    const float* g1 = (const float*)d_in[12];
    const float* be1 = (const float*)d_in[13];
    const float* g2 = (const float*)d_in[16];
    const float* be2 = (const float*)d_in[17];
    const float* W3 = (const float*)d_in[18];
    const float* b3 = (const float*)d_in[19];
    float* out = (float*)d_out;

    float *pXPf, *pXPr, *pY1, *pY2, *phf, *phr, *pgf, *pgr;
    __half *pXh, *pH1h, *pW1h, *pW2h, *pwfh, *pwrh;
    cudaGetSymbolAddress((void**)&pXPf, g_XPf);
    cudaGetSymbolAddress((void**)&pXPr, g_XPr);
    cudaGetSymbolAddress((void**)&pXh,  g_Xh);
    cudaGetSymbolAddress((void**)&pY1,  g_Y1);
    cudaGetSymbolAddress((void**)&pH1h, g_H1h);
    cudaGetSymbolAddress((void**)&pY2,  g_Y2);
    cudaGetSymbolAddress((void**)&phf,  g_hf);
    cudaGetSymbolAddress((void**)&phr,  g_hr);
    cudaGetSymbolAddress((void**)&pgf,  g_gf);
    cudaGetSymbolAddress((void**)&pgr,  g_gr);
    cudaGetSymbolAddress((void**)&pW1h, g_W1h);
    cudaGetSymbolAddress((void**)&pW2h, g_W2h);
    cudaGetSymbolAddress((void**)&pwfh, g_wihfh);
    cudaGetSymbolAddress((void**)&pwrh, g_wihrh);

    // 0. weight conversions (tiny)
    tohalf<<<(H1*MLPIN + 255)/256, 256>>>(W1, pW1h, H1*MLPIN);
    tohalf<<<(H2*H1   + 255)/256, 256>>>(W2, pW2h, H2*H1);
    tohalf<<<(G4*ED   + 255)/256, 256>>>(w_ih_f, pwfh, G4*ED);
    tohalf<<<(G4*ED   + 255)/256, 256>>>(w_ih_r, pwrh, G4*ED);

    // 1. init LSTM state
    zero_hc<<<(BB*HH + 255)/256, 256>>>();

    // 2. fill X fp16: state + V columns (must precede x_proj, which reads V from Xh)
    fill_X<<<RR, 128>>>(state, action);

    // 3. attention -> Xh[:,896:1024]
    attn_kernel<<<BB, 128>>>(action);

    // 4. x_proj both directions (tensor cores): XP = V @ w_ih^T  (bias folded into lstm_elem)
    hgemm_nt<<<dim3(G4/HBN_, RR/HBM_), 256>>>(pXh + 768, MLPIN, pwfh, ED, pXPf, G4, ED);
    hgemm_nt<<<dim3(G4/HBN_, RR/HBM_), 256>>>(pXh + 768, MLPIN, pwrh, ED, pXPr, G4, ED);

    // 5. LSTM recurrence, 32 steps, fwd+rev batched on z (fp32 for stability)
    for (int t = 0; t < KK; t++) {
        GemmPair P;
        P.A[0] = phf; P.A[1] = phr;
        P.W[0] = w_hh_f; P.W[1] = w_hh_r;
        P.C[0] = pgf; P.C[1] = pgr;
        gemm_nt<<<dim3(G4/TBN, BB/TBM, 2), 256>>>(P, G4, HH);
        lstm_elem<<<dim3((BB*HH + 255)/256, 1, 2), 256>>>(t, b_ih_f, b_hh_f, b_ih_r, b_hh_r);
    }

    // 6. MLP layer 1 (tensor cores; b1 dropped: BN is shift-invariant)
    hgemm_nt<<<dim3(H1/HBN_, RR/HBM_), 256>>>(pXh, MLPIN, pW1h, MLPIN, pY1, H1, MLPIN);
    bn_partial<<<dim3(H1/128, NCH), 128>>>(pY1, H1);
    bn_finalize<<<H1/128, 128>>>(H1);
    bn_apply_relu_h<<<2048, 256>>>(pY1, pH1h, g1, be1, H1);

    // 7. MLP layer 2 (tensor cores; b2 dropped likewise)
    hgemm_nt<<<dim3(H2/HBN_, RR/HBM_), 256>>>(pH1h, H1, pW2h, H1, pY2, H2, H1);
    bn_partial<<<dim3(H2/128, NCH), 128>>>(pY2, H2);
    bn_finalize<<<H2/128, 128>>>(H2);
    bn_apply_relu<<<2048, 256>>>(pY2, g2, be2, H2);

    // 8. final layer
    final_q<<<(RR*32 + 255)/256, 256>>>(W3, b3, out);

    // 9. regularizer
    {
        RegArgs ra;
        for (int i = 0; i < 18; i++) {
            ra.p[i] = (const float*)d_in[2 + i];
            ra.n[i] = in_sizes[2 + i];
        }
        reg_partial<<<dim3(18, 16), 256>>>(ra);
        reg_final<<<1, 32>>>(out, out_size);
    }
}

// round 7
// speedup vs baseline: 3.1578x; 1.1838x over previous
#include <cuda_runtime.h>
#include <cuda_fp16.h>
#include <mma.h>
#include <math.h>
#include <stdint.h>

using namespace nvcuda;

// ---------------- problem constants ----------------
#define BB 4096
#define KK 32
#define SD 512          // STATE_DIM
#define ED 128          // ENC_DIM
#define HH 128          // H
#define G4 512          // 4*H
#define RR (BB*KK)      // 131072 rows
#define MLPIN 1024
#define H1 1024
#define H2 512
#define NCH 64          // BN reduction chunks

// ---------------- device scratch ----------------
__device__ float  g_XPf[(size_t)RR*G4];    // x_proj forward (fp32)
__device__ float  g_XPr[(size_t)RR*G4];    // x_proj reverse (fp32)
__device__ __half g_Xh [(size_t)RR*MLPIN]; // MLP input fp16 (S|Of|Or|V|A)
__device__ float  g_Y1 [(size_t)RR*H1];    // pre-BN layer1
__device__ __half g_H1h[(size_t)RR*H1];    // post-BN+ReLU layer1 (fp16)
__device__ float  g_Y2 [(size_t)RR*H2];
__device__ float  g_psum[NCH*H1], g_psq[NCH*H1];
__device__ float  g_mean[H1], g_istd[H1];
__device__ float  g_regpart[18*16];
__device__ __half g_W1h[(size_t)H1*MLPIN];
__device__ __half g_W2h[(size_t)H2*H1];
__device__ __half g_wihfh[G4*ED], g_wihrh[G4*ED];

// ---------------- cp.async helpers ----------------
__device__ __forceinline__ void cp16(void* sm, const void* g) {
    uint32_t a = (uint32_t)__cvta_generic_to_shared(sm);
    asm volatile("cp.async.ca.shared.global [%0], [%1], 16;\n" :: "r"(a), "l"(g));
}
__device__ __forceinline__ void cp_commit() { asm volatile("cp.async.commit_group;\n"); }
template<int N> __device__ __forceinline__ void cp_wait() {
    asm volatile("cp.async.wait_group %0;\n" :: "n"(N));
}

// ---------------- fp32 -> fp16 convert ----------------
__global__ void tohalf(const float* __restrict__ src, __half* __restrict__ dst, int n) {
    int i = blockIdx.x * blockDim.x + threadIdx.x;
    if (i < n) dst[i] = __float2half(src[i]);
}

// ---------------- fp16 tensor-core GEMM, cp.async double-buffered ----------------
// C[M,N] = A[M,K] * B[N,K]^T, fp32 accumulate, no bias.
#define HBM_ 128
#define HBN_ 128
#define HBK_ 32
#define HLD_ 48   // smem row stride in halves

__global__ __launch_bounds__(256, 2)
void hgemm_nt(const __half* __restrict__ A, int lda,
              const __half* __restrict__ B, int ldb,
              float* __restrict__ C, int N, int K) {
    __shared__ __align__(16) __half As[2][HBM_ * HLD_];
    __shared__ __align__(16) __half Bs[2][HBN_ * HLD_];

    const int tid   = threadIdx.x;
    const int brow  = blockIdx.y * HBM_;
    const int bcol  = blockIdx.x * HBN_;
    const int warpid = tid >> 5;
    const int wm = warpid & 1;   // 64-row slab
    const int wn = warpid >> 1;  // 32-col slab

    wmma::fragment<wmma::accumulator, 16, 16, 16, float> c[4][2];
    #pragma unroll
    for (int i = 0; i < 4; i++)
        #pragma unroll
        for (int j = 0; j < 2; j++) wmma::fill_fragment(c[i][j], 0.0f);

    const int lr = tid >> 2;          // 0..63
    const int lc = (tid & 3) * 8;     // halves

    auto issue = [&](int st, int k0) {
        #pragma unroll
        for (int s = 0; s < 2; s++) {
            const int r = lr + s * 64;
            cp16(&As[st][r * HLD_ + lc], &A[(size_t)(brow + r) * lda + k0 + lc]);
            cp16(&Bs[st][r * HLD_ + lc], &B[(size_t)(bcol + r) * ldb + k0 + lc]);
        }
        cp_commit();
    };

    const int nt = K / HBK_;
    issue(0, 0);

    for (int i = 0; i < nt; i++) {
        const int st = i & 1;
        if (i + 1 < nt) { issue(st ^ 1, (i + 1) * HBK_); cp_wait<1>(); }
        else            { cp_wait<0>(); }
        __syncthreads();

        #pragma unroll
        for (int kk = 0; kk < HBK_; kk += 16) {
            wmma::fragment<wmma::matrix_a, 16, 16, 16, __half, wmma::row_major> af[4];
            wmma::fragment<wmma::matrix_b, 16, 16, 16, __half, wmma::col_major> bf[2];
            #pragma unroll
            for (int ii = 0; ii < 4; ii++)
                wmma::load_matrix_sync(af[ii], &As[st][(wm * 64 + ii * 16) * HLD_ + kk], HLD_);
            #pragma unroll
            for (int j = 0; j < 2; j++)
                wmma::load_matrix_sync(bf[j], &Bs[st][(wn * 32 + j * 16) * HLD_ + kk], HLD_);
            #pragma unroll
            for (int ii = 0; ii < 4; ii++)
                #pragma unroll
                for (int j = 0; j < 2; j++)
                    wmma::mma_sync(c[ii][j], af[ii], bf[j], c[ii][j]);
        }
        __syncthreads();
    }

    #pragma unroll
    for (int i = 0; i < 4; i++)
        #pragma unroll
        for (int j = 0; j < 2; j++)
            wmma::store_matrix_sync(
                &C[(size_t)(brow + wm * 64 + i * 16) * N + bcol + wn * 32 + j * 16],
                c[i][j], N, wmma::mem_row_major);
}

// ---------------- persistent fused bidirectional LSTM ----------------
// grid = (BB/LROWS, 2). One CTA: LROWS batch rows, all 32 steps, one direction.
// W_hh fp16 in smem; h fp16 in smem; c in registers; G tile via wmma into smem.
#define LROWS 32
#define LHLD  136      // half stride (128 + 8)
#define GLD   520      // float stride (512 + 8)

#define LSMEM_G     0
#define LSMEM_BIAS  (LSMEM_G + LROWS * GLD * 4)            // 66560
#define LSMEM_WHH   (LSMEM_BIAS + G4 * 4)                  // 68608
#define LSMEM_H     (LSMEM_WHH + G4 * LHLD * 2)            // 207872
#define LSMEM_TOTAL (LSMEM_H + LROWS * LHLD * 2)           // 216576

__global__ __launch_bounds__(256, 1)
void lstm_fused(const float* __restrict__ whh_f, const float* __restrict__ whh_r,
                const float* __restrict__ bihf, const float* __restrict__ bhhf,
                const float* __restrict__ bihr, const float* __restrict__ bhhr) {
    extern __shared__ char smem[];
    float*  sG    = (float*)(smem + LSMEM_G);
    float*  sBias = (float*)(smem + LSMEM_BIAS);
    __half* sWhh  = (__half*)(smem + LSMEM_WHH);
    __half* sH    = (__half*)(smem + LSMEM_H);

    const int z  = blockIdx.y;                 // 0 fwd, 1 rev
    const int b0 = blockIdx.x * LROWS;
    const int tid = threadIdx.x;
    const int warpid = tid >> 5;

    const float* Whh = z ? whh_r : whh_f;
    const float* XP  = z ? g_XPr : g_XPf;
    const float* bih = z ? bihr : bihf;
    const float* bhh = z ? bhhr : bhhf;
    const int colbase = z ? 640 : 512;

    // load W_hh -> smem fp16
    for (int i = tid; i < G4 * HH; i += 256) {
        const int n = i >> 7, k = i & 127;
        sWhh[n * LHLD + k] = __float2half(Whh[i]);
    }
    for (int i = tid; i < G4; i += 256) sBias[i] = bih[i] + bhh[i];
    for (int i = tid; i < LROWS * LHLD; i += 256) sH[i] = __float2half(0.f);

    float creg[16];
    #pragma unroll
    for (int e = 0; e < 16; e++) creg[e] = 0.f;
    __syncthreads();

    for (int t = 0; t < KK; t++) {
        const int k = z ? (KK - 1 - t) : t;

        // G[32,512] = H[32,128] @ Whh[512,128]^T ; warp owns 64 cols
        {
            wmma::fragment<wmma::accumulator, 16, 16, 16, float> acc[2][4];
            #pragma unroll
            for (int i = 0; i < 2; i++)
                #pragma unroll
                for (int j = 0; j < 4; j++) wmma::fill_fragment(acc[i][j], 0.0f);

            #pragma unroll
            for (int kk = 0; kk < HH; kk += 16) {
                wmma::fragment<wmma::matrix_a, 16, 16, 16, __half, wmma::row_major> a0, a1;
                wmma::load_matrix_sync(a0, &sH[0 * LHLD + kk], LHLD);
                wmma::load_matrix_sync(a1, &sH[16 * LHLD + kk], LHLD);
                #pragma unroll
                for (int j = 0; j < 4; j++) {
                    wmma::fragment<wmma::matrix_b, 16, 16, 16, __half, wmma::col_major> bfr;
                    wmma::load_matrix_sync(bfr, &sWhh[(warpid * 64 + j * 16) * LHLD + kk], LHLD);
                    wmma::mma_sync(acc[0][j], a0, bfr, acc[0][j]);
                    wmma::mma_sync(acc[1][j], a1, bfr, acc[1][j]);
                }
            }
            #pragma unroll
            for (int i = 0; i < 2; i++)
                #pragma unroll
                for (int j = 0; j < 4; j++)
                    wmma::store_matrix_sync(&sG[(i * 16) * GLD + warpid * 64 + j * 16],
                                            acc[i][j], GLD, wmma::mem_row_major);
        }
        __syncthreads();

        // gate update: thread e-loop covers 32x128 h elements
        #pragma unroll
        for (int e = 0; e < 16; e++) {
            const int idx = tid + 256 * e;
            const int row = idx >> 7;
            const int j   = idx & 127;
            const size_t r = (size_t)(b0 + row) * KK + k;
            const float* xp = XP + r * G4;
            const float* gr = sG + row * GLD;

            const float zi = xp[j]       + gr[j]       + sBias[j];
            const float zf = xp[128 + j] + gr[128 + j] + sBias[128 + j];
            const float zg = xp[256 + j] + gr[256 + j] + sBias[256 + j];
            const float zo = xp[384 + j] + gr[384 + j] + sBias[384 + j];

            const float si = 1.f / (1.f + expf(-zi));
            const float sf = 1.f / (1.f + expf(-zf));
            const float so = 1.f / (1.f + expf(-zo));

            const float cn = sf * creg[e] + si * tanhf(zg);
            const float hn = so * tanhf(cn);
            creg[e] = cn;

            sH[row * LHLD + j] = __float2half(hn);
            g_Xh[r * MLPIN + colbase + j] = __float2half(hn);
        }
        __syncthreads();
    }
}

// ---------------- fill X (fp16) with state + V ----------------
__global__ void fill_X(const float* __restrict__ state, const float* __restrict__ action) {
    const int r = blockIdx.x;
    const int tid = threadIdx.x;     // 128
    const int b = r >> 5;
    __half* xrow = g_Xh + (size_t)r * MLPIN;
    const float* srow = state + (size_t)b * SD;
    #pragma unroll
    for (int c = tid; c < SD; c += 128) xrow[c] = __float2half(srow[c]);
    xrow[768 + tid] = __float2half(action[(size_t)r * ED + tid]);
}

// ---------------- self-attention (per batch row, 32x32) ----------------
__global__ void attn_kernel(const float* __restrict__ V) {
    const int b = blockIdx.x;
    __shared__ float sV[32][129];
    __shared__ float sS[32][33];
    const int tid = threadIdx.x;  // 128
    const float* Vb = V + (size_t)b * KK * ED;

    for (int i = tid; i < KK * ED; i += 128) sV[i >> 7][i & 127] = Vb[i];
    __syncthreads();

    for (int idx = tid; idx < KK * KK; idx += 128) {
        const int r = idx >> 5, c = idx & 31;
        float s = 0.f;
        #pragma unroll 8
        for (int d = 0; d < ED; d++) s += sV[r][d] * sV[c][d];
        sS[r][c] = s;
    }
    __syncthreads();

    if (tid < KK) {
        float mx = -1e30f;
        for (int c = 0; c < KK; c++) mx = fmaxf(mx, sS[tid][c]);
        float sum = 0.f;
        for (int c = 0; c < KK; c++) { float e = expf(sS[tid][c] - mx); sS[tid][c] = e; sum += e; }
        float inv = 1.f / sum;
        for (int c = 0; c < KK; c++) sS[tid][c] *= inv;
    }
    __syncthreads();

    const int d = tid;
    for (int kq = 0; kq < KK; kq++) {
        float a = 0.f;
        #pragma unroll 8
        for (int l = 0; l < KK; l++) a += sS[kq][l] * sV[l][d];
        const size_t r = (size_t)b * KK + kq;
        g_Xh[r * MLPIN + 896 + d] = __float2half(a);
    }
}

// ---------------- batchnorm (deterministic two-pass) ----------------
__global__ void bn_partial(const float* __restrict__ Y, int cols) {
    const int c  = blockIdx.x * 128 + threadIdx.x;
    const int ch = blockIdx.y;
    const int rows_per = RR / NCH;
    const size_t r0 = (size_t)ch * rows_per;
    float s = 0.f, s2 = 0.f;
    const float* p = Y + r0 * cols + c;
    for (int i = 0; i < rows_per; i++) {
        float v = p[(size_t)i * cols];
        s += v; s2 += v * v;
    }
    g_psum[ch * cols + c] = s;
    g_psq [ch * cols + c] = s2;
}

__global__ void bn_finalize(int cols) {
    const int c = blockIdx.x * 128 + threadIdx.x;
    float s = 0.f, s2 = 0.f;
    for (int ch = 0; ch < NCH; ch++) { s += g_psum[ch * cols + c]; s2 += g_psq[ch * cols + c]; }
    const float mu  = s  / (float)RR;
    const float var = s2 / (float)RR - mu * mu;
    g_mean[c] = mu;
    g_istd[c] = rsqrtf(var + 1e-5f);
}

__global__ void bn_apply_relu_h(const float* __restrict__ Y, __half* __restrict__ out,
                                const float* __restrict__ gamma,
                                const float* __restrict__ beta, int cols) {
    const size_t total = (size_t)RR * cols;
    const int mask = cols - 1;
    size_t i = (size_t)blockIdx.x * blockDim.x + threadIdx.x;
    const size_t stride = (size_t)gridDim.x * blockDim.x;
    for (; i < total; i += stride) {
        const int c = (int)(i & mask);
        float v = (Y[i] - g_mean[c]) * g_istd[c] * gamma[c] + beta[c];
        out[i] = __float2half(v > 0.f ? v : 0.f);
    }
}

__global__ void bn_apply_relu(float* Y, const float* __restrict__ gamma,
                              const float* __restrict__ beta, int cols) {
    const size_t total = (size_t)RR * cols;
    const int mask = cols - 1;
    size_t i = (size_t)blockIdx.x * blockDim.x + threadIdx.x;
    const size_t stride = (size_t)gridDim.x * blockDim.x;
    for (; i < total; i += stride) {
        const int c = (int)(i & mask);
        float v = (Y[i] - g_mean[c]) * g_istd[c] * gamma[c] + beta[c];
        Y[i] = v > 0.f ? v : 0.f;
    }
}

// ---------------- final layer: Q = h2 @ W3^T + b3 ----------------
__global__ void final_q(const float* __restrict__ W3, const float* __restrict__ b3,
                        float* __restrict__ out) {
    const int gwarp = (blockIdx.x * blockDim.x + threadIdx.x) >> 5;
    const int lane  = threadIdx.x & 31;
    if (gwarp >= RR) return;
    const float* row = g_Y2 + (size_t)gwarp * H2;
    float s = 0.f;
    #pragma unroll
    for (int i = 0; i < H2 / 32; i++) {
        const int c = i * 32 + lane;
        s += row[c] * W3[c];
    }
    #pragma unroll
    for (int o = 16; o; o >>= 1) s += __shfl_xor_sync(0xffffffffu, s, o);
    if (lane == 0) out[gwarp] = s + b3[0];
}

// ---------------- regularizer ----------------
struct RegArgs { const float* p[18]; int n[18]; };

__global__ void reg_partial(RegArgs ra) {
    const int pi = blockIdx.x;
    const int ch = blockIdx.y;
    __shared__ float red[256];
    const float* p = ra.p[pi];
    const int n = ra.n[pi];
    const int per = (n + 15) / 16;
    const int lo = ch * per;
    const int hi = min(n, lo + per);
    float s = 0.f;
    for (int i = lo + threadIdx.x; i < hi; i += 256) { float v = p[i]; s += v * v; }
    red[threadIdx.x] = s;
    __syncthreads();
    for (int o = 128; o; o >>= 1) {
        if (threadIdx.x < o) red[threadIdx.x] += red[threadIdx.x + o];
        __syncthreads();
    }
    if (threadIdx.x == 0) g_regpart[pi * 16 + ch] = red[0] / (float)n;
}

__global__ void reg_final(float* out, int out_size) {
    if (threadIdx.x == 0 && blockIdx.x == 0) {
        float s = 0.f;
        for (int i = 0; i < 18 * 16; i++) s += g_regpart[i];
        if (out_size > RR) out[RR] = s;
    }
}

// ---------------- launch ----------------
extern "C" void kernel_launch(void* const* d_in, const int* in_sizes, int n_in,
                              void* d_out, int out_size) {
    const float* state  = (const float*)d_in[0];
    const float* action = (const float*)d_in[1];
    const float* w_ih_f = (const float*)d_in[2];
    const float* w_hh_f = (const float*)d_in[3];
    const float* b_ih_f = (const float*)d_in[4];
    const float* b_hh_f = (const float*)d_in[5];
    const float* w_ih_r = (const float*)d_in[6];
    const float* w_hh_r = (const float*)d_in[7];
    const float* b_ih_r = (const float*)d_in[8];
    const float* b_hh_r = (const float*)d_in[9];
    const float* W1 = (const float*)d_in[10];
    const float* g1 = (const float*)d_in[12];
    const float* be1 = (const float*)d_in[13];
    const float* W2 = (const float*)d_in[14];
    const float* g2 = (const float*)d_in[16];
    const float* be2 = (const float*)d_in[17];
    const float* W3 = (const float*)d_in[18];
    const float* b3 = (const float*)d_in[19];
    float* out = (float*)d_out;

    float *pXPf, *pXPr, *pY1, *pY2;
    __half *pXh, *pH1h, *pW1h, *pW2h, *pwfh, *pwrh;
    cudaGetSymbolAddress((void**)&pXPf, g_XPf);
    cudaGetSymbolAddress((void**)&pXPr, g_XPr);
    cudaGetSymbolAddress((void**)&pXh,  g_Xh);
    cudaGetSymbolAddress((void**)&pY1,  g_Y1);
    cudaGetSymbolAddress((void**)&pH1h, g_H1h);
    cudaGetSymbolAddress((void**)&pY2,  g_Y2);
    cudaGetSymbolAddress((void**)&pW1h, g_W1h);
    cudaGetSymbolAddress((void**)&pW2h, g_W2h);
    cudaGetSymbolAddress((void**)&pwfh, g_wihfh);
    cudaGetSymbolAddress((void**)&pwrh, g_wihrh);

    cudaFuncSetAttribute(lstm_fused, cudaFuncAttributeMaxDynamicSharedMemorySize, LSMEM_TOTAL);

    // 0. weight conversions (tiny)
    tohalf<<<(H1*MLPIN + 255)/256, 256>>>(W1, pW1h, H1*MLPIN);
    tohalf<<<(H2*H1   + 255)/256, 256>>>(W2, pW2h, H2*H1);
    tohalf<<<(G4*ED   + 255)/256, 256>>>(w_ih_f, pwfh, G4*ED);
    tohalf<<<(G4*ED   + 255)/256, 256>>>(w_ih_r, pwrh, G4*ED);

    // 1. fill X fp16: state + V columns (x_proj reads V from Xh)
    fill_X<<<RR, 128>>>(state, action);

    // 2. attention -> Xh[:,896:1024]
    attn_kernel<<<BB, 128>>>(action);

    // 3. x_proj both directions (tensor cores); bias folded into lstm_fused
    hgemm_nt<<<dim3(G4/HBN_, RR/HBM_), 256>>>(pXh + 768, MLPIN, pwfh, ED, pXPf, G4, ED);
    hgemm_nt<<<dim3(G4/HBN_, RR/HBM_), 256>>>(pXh + 768, MLPIN, pwrh, ED, pXPr, G4, ED);

    // 4. fused persistent LSTM (both directions), one launch
    lstm_fused<<<dim3(BB/LROWS, 2), 256, LSMEM_TOTAL>>>(w_hh_f, w_hh_r,
                                                        b_ih_f, b_hh_f, b_ih_r, b_hh_r);

    // 5. MLP layer 1 (b1 dropped: BN shift-invariant)
    hgemm_nt<<<dim3(H1/HBN_, RR/HBM_), 256>>>(pXh, MLPIN, pW1h, MLPIN, pY1, H1, MLPIN);
    bn_partial<<<dim3(H1/128, NCH), 128>>>(pY1, H1);
    bn_finalize<<<H1/128, 128>>>(H1);
    bn_apply_relu_h<<<2048, 256>>>(pY1, pH1h, g1, be1, H1);

    // 6. MLP layer 2 (b2 dropped)
    hgemm_nt<<<dim3(H2/HBN_, RR/HBM_), 256>>>(pH1h, H1, pW2h, H1, pY2, H2, H1);
    bn_partial<<<dim3(H2/128, NCH), 128>>>(pY2, H2);
    bn_finalize<<<H2/128, 128>>>(H2);
    bn_apply_relu<<<2048, 256>>>(pY2, g2, be2, H2);

    // 7. final layer
    final_q<<<(RR*32 + 255)/256, 256>>>(W3, b3, out);

    // 8. regularizer
    {
        RegArgs ra;
        for (int i = 0; i < 18; i++) {
            ra.p[i] = (const float*)d_in[2 + i];
            ra.n[i] = in_sizes[2 + i];
        }
        reg_partial<<<dim3(18, 16), 256>>>(ra);
        reg_final<<<1, 32>>>(out, out_size);
    }
}

// round 8
// speedup vs baseline: 3.3569x; 1.0630x over previous
#include <cuda_runtime.h>
#include <cuda_fp16.h>
#include <mma.h>
#include <math.h>
#include <stdint.h>

using namespace nvcuda;

// ---------------- problem constants ----------------
#define BB 4096
#define KK 32
#define SD 512          // STATE_DIM
#define ED 128          // ENC_DIM
#define HH 128          // H
#define G4 512          // 4*H
#define RR (BB*KK)      // 131072 rows
#define MLPIN 1024
#define H1 1024
#define H2 512
#define NRB (RR/128)    // 1024 GEMM row-blocks

// ---------------- device scratch ----------------
__device__ float  g_XPf[(size_t)RR*G4];    // x_proj forward (fp32)
__device__ float  g_XPr[(size_t)RR*G4];    // x_proj reverse (fp32)
__device__ __half g_Xh [(size_t)RR*MLPIN]; // MLP input fp16 (S|Of|Or|V|A)
__device__ float  g_Y1 [(size_t)RR*H1];    // pre-BN layer1
__device__ __half g_H1h[(size_t)RR*H1];    // post-BN+ReLU layer1 (fp16)
__device__ float  g_Y2 [(size_t)RR*H2];
__device__ float  g_bnsum[NRB*H1], g_bnsq[NRB*H1];   // per-rowblock BN partials
__device__ float  g_mean[H1], g_istd[H1];
__device__ float  g_regpart[18*16];
__device__ __half g_W1h[(size_t)H1*MLPIN];
__device__ __half g_W2h[(size_t)H2*H1];
__device__ __half g_wihfh[G4*ED], g_wihrh[G4*ED];

// ---------------- cp.async helpers ----------------
__device__ __forceinline__ void cp16(void* sm, const void* g) {
    uint32_t a = (uint32_t)__cvta_generic_to_shared(sm);
    asm volatile("cp.async.ca.shared.global [%0], [%1], 16;\n" :: "r"(a), "l"(g));
}
__device__ __forceinline__ void cp_commit() { asm volatile("cp.async.commit_group;\n"); }
template<int N> __device__ __forceinline__ void cp_wait() {
    asm volatile("cp.async.wait_group %0;\n" :: "n"(N));
}

// ---------------- fp32 -> fp16 convert ----------------
__global__ void tohalf(const float* __restrict__ src, __half* __restrict__ dst, int n) {
    int i = blockIdx.x * blockDim.x + threadIdx.x;
    if (i < n) dst[i] = __float2half(src[i]);
}

// ---------------- fp16 tensor-core GEMM, 3-stage cp.async ----------------
// C[M,N] = A[M,K] * B[N,K]^T, fp32 accumulate, no bias.
// DO_BN: epilogue computes per-rowblock column sum/sumsq partials.
#define HBM_ 128
#define HBN_ 128
#define HBK_ 32
#define HLD_ 48        // smem row stride in halves
#define STG_ 3
#define HTILE (HBM_ * HLD_)
#define HG_SMEM (STG_ * 2 * HTILE * 2)   // bytes = 73728

template<int DO_BN>
__global__ __launch_bounds__(256, 2)
void hgemm_nt(const __half* __restrict__ A, int lda,
              const __half* __restrict__ B, int ldb,
              float* __restrict__ C, int N, int K) {
    extern __shared__ __align__(16) char dynsm[];
    __half* As = (__half*)dynsm;
    __half* Bs = As + STG_ * HTILE;

    const int tid   = threadIdx.x;
    const int brow  = blockIdx.y * HBM_;
    const int bcol  = blockIdx.x * HBN_;
    const int warpid = tid >> 5;
    const int wm = warpid & 1;   // 64-row slab
    const int wn = warpid >> 1;  // 32-col slab

    wmma::fragment<wmma::accumulator, 16, 16, 16, float> c[4][2];
    #pragma unroll
    for (int i = 0; i < 4; i++)
        #pragma unroll
        for (int j = 0; j < 2; j++) wmma::fill_fragment(c[i][j], 0.0f);

    const int lr = tid >> 2;          // 0..63
    const int lc = (tid & 3) * 8;     // halves

    auto issue = [&](int st, int k0) {
        #pragma unroll
        for (int s = 0; s < 2; s++) {
            const int r = lr + s * 64;
            cp16(&As[st * HTILE + r * HLD_ + lc], &A[(size_t)(brow + r) * lda + k0 + lc]);
            cp16(&Bs[st * HTILE + r * HLD_ + lc], &B[(size_t)(bcol + r) * ldb + k0 + lc]);
        }
        cp_commit();
    };

    const int nt = K / HBK_;   // >= 4 for all our shapes
    issue(0, 0); issue(1, HBK_); issue(2, 2 * HBK_);

    for (int i = 0; i < nt; i++) {
        const int st = i % STG_;
        if (i <= nt - STG_)      cp_wait<STG_-1>();
        else if (i == nt - 2)    cp_wait<1>();
        else                     cp_wait<0>();
        __syncthreads();

        #pragma unroll
        for (int kk = 0; kk < HBK_; kk += 16) {
            wmma::fragment<wmma::matrix_a, 16, 16, 16, __half, wmma::row_major> af[4];
            wmma::fragment<wmma::matrix_b, 16, 16, 16, __half, wmma::col_major> bf[2];
            #pragma unroll
            for (int ii = 0; ii < 4; ii++)
                wmma::load_matrix_sync(af[ii], &As[st * HTILE + (wm * 64 + ii * 16) * HLD_ + kk], HLD_);
            #pragma unroll
            for (int j = 0; j < 2; j++)
                wmma::load_matrix_sync(bf[j], &Bs[st * HTILE + (wn * 32 + j * 16) * HLD_ + kk], HLD_);
            #pragma unroll
            for (int ii = 0; ii < 4; ii++)
                #pragma unroll
                for (int j = 0; j < 2; j++)
                    wmma::mma_sync(c[ii][j], af[ii], bf[j], c[ii][j]);
        }
        __syncthreads();
        if (i + STG_ < nt) issue(st, (i + STG_) * HBK_);
    }

    #pragma unroll
    for (int i = 0; i < 4; i++)
        #pragma unroll
        for (int j = 0; j < 2; j++)
            wmma::store_matrix_sync(
                &C[(size_t)(brow + wm * 64 + i * 16) * N + bcol + wn * 32 + j * 16],
                c[i][j], N, wmma::mem_row_major);

    if (DO_BN) {
        // __syncthreads makes prior global writes visible block-wide
        __syncthreads();
        __shared__ float redS[256], redQ[256];
        const int col = tid & 127;
        const int hh  = tid >> 7;          // 0..1 -> 64-row halves
        const float* cp = C + (size_t)(brow + hh * 64) * N + bcol + col;
        float s = 0.f, s2 = 0.f;
        #pragma unroll 8
        for (int r = 0; r < 64; r++) {
            float v = cp[(size_t)r * N];
            s += v; s2 += v * v;
        }
        redS[tid] = s; redQ[tid] = s2;
        __syncthreads();
        if (tid < 128) {
            g_bnsum[(size_t)blockIdx.y * N + bcol + tid] = redS[tid] + redS[tid + 128];
            g_bnsq [(size_t)blockIdx.y * N + bcol + tid] = redQ[tid] + redQ[tid + 128];
        }
    }
}

// ---------------- persistent fused bidirectional LSTM ----------------
#define LROWS 32
#define LHLD  136      // half stride (128 + 8)
#define GLD   520      // float stride (512 + 8)

#define LSMEM_G     0
#define LSMEM_BIAS  (LSMEM_G + LROWS * GLD * 4)
#define LSMEM_WHH   (LSMEM_BIAS + G4 * 4)
#define LSMEM_H     (LSMEM_WHH + G4 * LHLD * 2)
#define LSMEM_TOTAL (LSMEM_H + LROWS * LHLD * 2)

__global__ __launch_bounds__(256, 1)
void lstm_fused(const float* __restrict__ whh_f, const float* __restrict__ whh_r,
                const float* __restrict__ bihf, const float* __restrict__ bhhf,
                const float* __restrict__ bihr, const float* __restrict__ bhhr) {
    extern __shared__ char smem[];
    float*  sG    = (float*)(smem + LSMEM_G);
    float*  sBias = (float*)(smem + LSMEM_BIAS);
    __half* sWhh  = (__half*)(smem + LSMEM_WHH);
    __half* sH    = (__half*)(smem + LSMEM_H);

    const int z  = blockIdx.y;
    const int b0 = blockIdx.x * LROWS;
    const int tid = threadIdx.x;
    const int warpid = tid >> 5;

    const float* Whh = z ? whh_r : whh_f;
    const float* XP  = z ? g_XPr : g_XPf;
    const float* bih = z ? bihr : bihf;
    const float* bhh = z ? bhhr : bhhf;
    const int colbase = z ? 640 : 512;

    for (int i = tid; i < G4 * HH; i += 256) {
        const int n = i >> 7, k = i & 127;
        sWhh[n * LHLD + k] = __float2half(Whh[i]);
    }
    for (int i = tid; i < G4; i += 256) sBias[i] = bih[i] + bhh[i];
    for (int i = tid; i < LROWS * LHLD; i += 256) sH[i] = __float2half(0.f);

    float creg[16];
    #pragma unroll
    for (int e = 0; e < 16; e++) creg[e] = 0.f;
    __syncthreads();

    for (int t = 0; t < KK; t++) {
        const int k = z ? (KK - 1 - t) : t;
        {
            wmma::fragment<wmma::accumulator, 16, 16, 16, float> acc[2][4];
            #pragma unroll
            for (int i = 0; i < 2; i++)
                #pragma unroll
                for (int j = 0; j < 4; j++) wmma::fill_fragment(acc[i][j], 0.0f);

            #pragma unroll
            for (int kk = 0; kk < HH; kk += 16) {
                wmma::fragment<wmma::matrix_a, 16, 16, 16, __half, wmma::row_major> a0, a1;
                wmma::load_matrix_sync(a0, &sH[0 * LHLD + kk], LHLD);
                wmma::load_matrix_sync(a1, &sH[16 * LHLD + kk], LHLD);
                #pragma unroll
                for (int j = 0; j < 4; j++) {
                    wmma::fragment<wmma::matrix_b, 16, 16, 16, __half, wmma::col_major> bfr;
                    wmma::load_matrix_sync(bfr, &sWhh[(warpid * 64 + j * 16) * LHLD + kk], LHLD);
                    wmma::mma_sync(acc[0][j], a0, bfr, acc[0][j]);
                    wmma::mma_sync(acc[1][j], a1, bfr, acc[1][j]);
                }
            }
            #pragma unroll
            for (int i = 0; i < 2; i++)
                #pragma unroll
                for (int j = 0; j < 4; j++)
                    wmma::store_matrix_sync(&sG[(i * 16) * GLD + warpid * 64 + j * 16],
                                            acc[i][j], GLD, wmma::mem_row_major);
        }
        __syncthreads();

        #pragma unroll
        for (int e = 0; e < 16; e++) {
            const int idx = tid + 256 * e;
            const int row = idx >> 7;
            const int j   = idx & 127;
            const size_t r = (size_t)(b0 + row) * KK + k;
            const float* xp = XP + r * G4;
            const float* gr = sG + row * GLD;

            const float zi = xp[j]       + gr[j]       + sBias[j];
            const float zf = xp[128 + j] + gr[128 + j] + sBias[128 + j];
            const float zg = xp[256 + j] + gr[256 + j] + sBias[256 + j];
            const float zo = xp[384 + j] + gr[384 + j] + sBias[384 + j];

            const float si = 1.f / (1.f + expf(-zi));
            const float sf = 1.f / (1.f + expf(-zf));
            const float so = 1.f / (1.f + expf(-zo));

            const float cn = sf * creg[e] + si * tanhf(zg);
            const float hn = so * tanhf(cn);
            creg[e] = cn;

            sH[row * LHLD + j] = __float2half(hn);
            g_Xh[r * MLPIN + colbase + j] = __float2half(hn);
        }
        __syncthreads();
    }
}

// ---------------- fill X (fp16) with state + V ----------------
__global__ void fill_X(const float* __restrict__ state, const float* __restrict__ action) {
    const int r = blockIdx.x;
    const int tid = threadIdx.x;     // 128
    const int b = r >> 5;
    __half* xrow = g_Xh + (size_t)r * MLPIN;
    const float* srow = state + (size_t)b * SD;
    #pragma unroll
    for (int c = tid; c < SD; c += 128) xrow[c] = __float2half(srow[c]);
    xrow[768 + tid] = __float2half(action[(size_t)r * ED + tid]);
}

// ---------------- self-attention, register-blocked ----------------
#define VLD 133
__global__ __launch_bounds__(128)
void attn_kernel(const float* __restrict__ V) {
    const int b = blockIdx.x;
    __shared__ float sV[32 * VLD];
    __shared__ float sS[32 * 33];
    const int tid = threadIdx.x;  // 128
    const float* Vb = V + (size_t)b * KK * ED;

    for (int i = tid; i < KK * ED; i += 128)
        sV[(i >> 7) * VLD + (i & 127)] = Vb[i];
    __syncthreads();

    // S = V V^T : thread -> 2 rows x 4 cols
    {
        const int rp = tid >> 3;       // 0..15
        const int cq = tid & 7;        // 0..7
        float acc[2][4];
        #pragma unroll
        for (int i = 0; i < 2; i++)
            #pragma unroll
            for (int j = 0; j < 4; j++) acc[i][j] = 0.f;

        #pragma unroll 4
        for (int d = 0; d < ED; d++) {
            const float a0 = sV[(2 * rp)     * VLD + d];
            const float a1 = sV[(2 * rp + 1) * VLD + d];
            #pragma unroll
            for (int j = 0; j < 4; j++) {
                const float bv = sV[(4 * cq + j) * VLD + d];
                acc[0][j] += a0 * bv;
                acc[1][j] += a1 * bv;
            }
        }
        #pragma unroll
        for (int i = 0; i < 2; i++)
            #pragma unroll
            for (int j = 0; j < 4; j++)
                sS[(2 * rp + i) * 33 + 4 * cq + j] = acc[i][j];
    }
    __syncthreads();

    if (tid < KK) {
        float mx = -1e30f;
        for (int c = 0; c < KK; c++) mx = fmaxf(mx, sS[tid * 33 + c]);
        float sum = 0.f;
        for (int c = 0; c < KK; c++) { float e = expf(sS[tid * 33 + c] - mx); sS[tid * 33 + c] = e; sum += e; }
        float inv = 1.f / sum;
        for (int c = 0; c < KK; c++) sS[tid * 33 + c] *= inv;
    }
    __syncthreads();

    // A = P V : thread owns column d, 32 accumulators
    {
        float a[32];
        #pragma unroll
        for (int k = 0; k < 32; k++) a[k] = 0.f;
        #pragma unroll 4
        for (int l = 0; l < 32; l++) {
            const float vl = sV[l * VLD + tid];
            #pragma unroll
            for (int k = 0; k < 32; k++) a[k] += sS[k * 33 + l] * vl;
        }
        #pragma unroll
        for (int k = 0; k < 32; k++) {
            const size_t r = (size_t)b * KK + k;
            g_Xh[r * MLPIN + 896 + tid] = __float2half(a[k]);
        }
    }
}

// ---------------- BN finalize over 1024 row-block partials ----------------
__global__ void bn_finalize(int cols) {
    const int c = blockIdx.x * 128 + threadIdx.x;
    float s = 0.f, s2 = 0.f;
    for (int rb = 0; rb < NRB; rb++) {
        s  += g_bnsum[(size_t)rb * cols + c];
        s2 += g_bnsq [(size_t)rb * cols + c];
    }
    const float mu  = s  / (float)RR;
    const float var = s2 / (float)RR - mu * mu;
    g_mean[c] = mu;
    g_istd[c] = rsqrtf(var + 1e-5f);
}

// ---------------- layer-1 BN+ReLU -> fp16 ----------------
__global__ void bn_apply_relu_h(const float* __restrict__ Y, __half* __restrict__ out,
                                const float* __restrict__ gamma,
                                const float* __restrict__ beta, int cols) {
    const size_t total = (size_t)RR * cols;
    const int mask = cols - 1;
    size_t i = (size_t)blockIdx.x * blockDim.x + threadIdx.x;
    const size_t stride = (size_t)gridDim.x * blockDim.x;
    for (; i < total; i += stride) {
        const int c = (int)(i & mask);
        float v = (Y[i] - g_mean[c]) * g_istd[c] * gamma[c] + beta[c];
        out[i] = __float2half(v > 0.f ? v : 0.f);
    }
}

// ---------------- final layer with fused layer-2 BN+ReLU ----------------
__global__ __launch_bounds__(256)
void final_q(const float* __restrict__ W3, const float* __restrict__ b3,
             const float* __restrict__ g2, const float* __restrict__ be2,
             float* __restrict__ out) {
    __shared__ float sw[H2], smu[H2], sis[H2], sg[H2], sb[H2];
    const int tid = threadIdx.x;
    for (int i = tid; i < H2; i += 256) {
        sw[i] = W3[i]; smu[i] = g_mean[i]; sis[i] = g_istd[i];
        sg[i] = g2[i]; sb[i] = be2[i];
    }
    __syncthreads();

    const int warp = tid >> 5, lane = tid & 31;
    const size_t row = (size_t)blockIdx.x * 8 + warp;
    const float* y = g_Y2 + row * H2;
    float s = 0.f;
    #pragma unroll
    for (int i = 0; i < H2 / 32; i++) {
        const int c = i * 32 + lane;
        float v = (y[c] - smu[c]) * sis[c] * sg[c] + sb[c];
        v = fmaxf(v, 0.f);
        s += v * sw[c];
    }
    #pragma unroll
    for (int o = 16; o; o >>= 1) s += __shfl_xor_sync(0xffffffffu, s, o);
    if (lane == 0) out[row] = s + b3[0];
}

// ---------------- regularizer ----------------
struct RegArgs { const float* p[18]; int n[18]; };

__global__ void reg_partial(RegArgs ra) {
    const int pi = blockIdx.x;
    const int ch = blockIdx.y;
    __shared__ float red[256];
    const float* p = ra.p[pi];
    const int n = ra.n[pi];
    const int per = (n + 15) / 16;
    const int lo = ch * per;
    const int hi = min(n, lo + per);
    float s = 0.f;
    for (int i = lo + threadIdx.x; i < hi; i += 256) { float v = p[i]; s += v * v; }
    red[threadIdx.x] = s;
    __syncthreads();
    for (int o = 128; o; o >>= 1) {
        if (threadIdx.x < o) red[threadIdx.x] += red[threadIdx.x + o];
        __syncthreads();
    }
    if (threadIdx.x == 0) g_regpart[pi * 16 + ch] = red[0] / (float)n;
}

__global__ void reg_final(float* out, int out_size) {
    if (threadIdx.x == 0 && blockIdx.x == 0) {
        float s = 0.f;
        for (int i = 0; i < 18 * 16; i++) s += g_regpart[i];
        if (out_size > RR) out[RR] = s;
    }
}

// ---------------- launch ----------------
extern "C" void kernel_launch(void* const* d_in, const int* in_sizes, int n_in,
                              void* d_out, int out_size) {
    const float* state  = (const float*)d_in[0];
    const float* action = (const float*)d_in[1];
    const float* w_ih_f = (const float*)d_in[2];
    const float* w_hh_f = (const float*)d_in[3];
    const float* b_ih_f = (const float*)d_in[4];
    const float* b_hh_f = (const float*)d_in[5];
    const float* w_ih_r = (const float*)d_in[6];
    const float* w_hh_r = (const float*)d_in[7];
    const float* b_ih_r = (const float*)d_in[8];
    const float* b_hh_r = (const float*)d_in[9];
    const float* W1 = (const float*)d_in[10];
    const float* g1 = (const float*)d_in[12];
    const float* be1 = (const float*)d_in[13];
    const float* W2 = (const float*)d_in[14];
    const float* g2 = (const float*)d_in[16];
    const float* be2 = (const float*)d_in[17];
    const float* W3 = (const float*)d_in[18];
    const float* b3 = (const float*)d_in[19];
    float* out = (float*)d_out;

    float *pXPf, *pXPr, *pY1, *pY2;
    __half *pXh, *pH1h, *pW1h, *pW2h, *pwfh, *pwrh;
    cudaGetSymbolAddress((void**)&pXPf, g_XPf);
    cudaGetSymbolAddress((void**)&pXPr, g_XPr);
    cudaGetSymbolAddress((void**)&pXh,  g_Xh);
    cudaGetSymbolAddress((void**)&pY1,  g_Y1);
    cudaGetSymbolAddress((void**)&pH1h, g_H1h);
    cudaGetSymbolAddress((void**)&pY2,  g_Y2);
    cudaGetSymbolAddress((void**)&pW1h, g_W1h);
    cudaGetSymbolAddress((void**)&pW2h, g_W2h);
    cudaGetSymbolAddress((void**)&pwfh, g_wihfh);
    cudaGetSymbolAddress((void**)&pwrh, g_wihrh);

    cudaFuncSetAttribute(lstm_fused, cudaFuncAttributeMaxDynamicSharedMemorySize, LSMEM_TOTAL);
    cudaFuncSetAttribute(hgemm_nt<0>, cudaFuncAttributeMaxDynamicSharedMemorySize, HG_SMEM);
    cudaFuncSetAttribute(hgemm_nt<1>, cudaFuncAttributeMaxDynamicSharedMemorySize, HG_SMEM);

    // 0. weight conversions (tiny)
    tohalf<<<(H1*MLPIN + 255)/256, 256>>>(W1, pW1h, H1*MLPIN);
    tohalf<<<(H2*H1   + 255)/256, 256>>>(W2, pW2h, H2*H1);
    tohalf<<<(G4*ED   + 255)/256, 256>>>(w_ih_f, pwfh, G4*ED);
    tohalf<<<(G4*ED   + 255)/256, 256>>>(w_ih_r, pwrh, G4*ED);

    // 1. fill X fp16: state + V columns
    fill_X<<<RR, 128>>>(state, action);

    // 2. attention -> Xh[:,896:1024]
    attn_kernel<<<BB, 128>>>(action);

    // 3. x_proj both directions (tensor cores)
    hgemm_nt<0><<<dim3(G4/HBN_, RR/HBM_), 256, HG_SMEM>>>(pXh + 768, MLPIN, pwfh, ED, pXPf, G4, ED);
    hgemm_nt<0><<<dim3(G4/HBN_, RR/HBM_), 256, HG_SMEM>>>(pXh + 768, MLPIN, pwrh, ED, pXPr, G4, ED);

    // 4. fused persistent LSTM (both directions), one launch
    lstm_fused<<<dim3(BB/LROWS, 2), 256, LSMEM_TOTAL>>>(w_hh_f, w_hh_r,
                                                        b_ih_f, b_hh_f, b_ih_r, b_hh_r);

    // 5. MLP layer 1 + fused BN stats (b1 dropped: BN shift-invariant)
    hgemm_nt<1><<<dim3(H1/HBN_, RR/HBM_), 256, HG_SMEM>>>(pXh, MLPIN, pW1h, MLPIN, pY1, H1, MLPIN);
    bn_finalize<<<H1/128, 128>>>(H1);
    bn_apply_relu_h<<<2048, 256>>>(pY1, pH1h, g1, be1, H1);

    // 6. MLP layer 2 + fused BN stats (b2 dropped)
    hgemm_nt<1><<<dim3(H2/HBN_, RR/HBM_), 256, HG_SMEM>>>(pH1h, H1, pW2h, H1, pY2, H2, H1);
    bn_finalize<<<H2/128, 128>>>(H2);

    // 7. final layer with fused layer-2 BN+ReLU
    final_q<<<RR/8, 256>>>(W3, b3, g2, be2, out);

    // 8. regularizer
    {
        RegArgs ra;
        for (int i = 0; i < 18; i++) {
            ra.p[i] = (const float*)d_in[2 + i];
            ra.n[i] = in_sizes[2 + i];
        }
        reg_partial<<<dim3(18, 16), 256>>>(ra);
        reg_final<<<1, 32>>>(out, out_size);
    }
}